// round 8
// baseline (speedup 1.0000x reference)
#include <cuda_runtime.h>
#include <cuda_fp16.h>
#include <cstdint>

#define BATCH   16384
#define IN_DIM  4096
#define OUT_DIM 64
#define BM      64
#define XCH     64                 // x-cols per superchunk
#define KCH     192                // feature halfs per superchunk
#define NCH2    (IN_DIM / XCH)     // 64 superchunks
#define NS      12                 // m16n8k16 k-steps per superchunk
#define THREADS 256

#define A_ROW_W  100               // words per A row: 96 data (192 halfs) + 4 pad
#define A_BUF_W  (BM * A_ROW_W)    // 6400 words
#define B_BUF_W  (NS * 4 * 32 * 4) // 6144 words
#define SMEM_BYTES ((2 * A_BUF_W + 2 * B_BUF_W) * 4)   // 100352 B

// Fragment-ordered fp16 weights, superchunk-major, pair-packed per warp-column:
// word w: reg=w&1, nl=(w>>1)&1, lane=(w>>2)&31, ntp=(w>>7)&3, s=(w>>9)%12, q=(w>>9)/12
// halfs: k_local = 16s + 2*(lane&3) + 8*reg + h ;  n = (ntp*2+nl)*8 + (lane>>2)
__device__ __align__(16) __half2 g_w2[NCH2 * B_BUF_W];

__device__ __forceinline__ float tanh_fast(float v) {
    float o;
    asm("tanh.approx.f32 %0, %1;" : "=f"(o) : "f"(v));
    return o;
}

// Verified cubic B-spline basis (knots [-1,-.5,0,.5,1,(1)]) + silu(tanh form).
__device__ __forceinline__ void kan_features(float xv, float& b0, float& b1, float& si) {
    float xc = fminf(fmaxf(xv, -1.0f), 1.0f);
    float y1 = xc + 1.0f;
    float y2 = fmaxf(xc + 0.5f, 0.0f);
    float y3 = fmaxf(xc, 0.0f);
    float y4 = fmaxf(xc - 0.5f, 0.0f);
    float c1 = y1 * y1 * y1;
    float c2 = y2 * y2 * y2;
    float c3 = y3 * y3 * y3;
    float c4 = y4 * y4 * y4;
    const float k43  = 1.3333333333333333f;
    const float k163 = 5.3333333333333333f;
    b0 = fmaf(k43, c1, fmaf(-k163, c2, fmaf(8.0f, c3, -k163 * c4)));
    b1 = fmaf(k43, c2, fmaf(-6.0f, c3, 12.0f * c4));
    float xh = 0.5f * xv;
    si = fmaf(xh, tanh_fast(xh), xh);    // x*sigmoid(x) = 0.5x(1+tanh(x/2))
}

__global__ void prep_weights_kernel(const float* __restrict__ c,
                                    const float* __restrict__ ws,
                                    const float* __restrict__ wb) {
    int w = blockIdx.x * blockDim.x + threadIdx.x;
    if (w >= NCH2 * B_BUF_W) return;
    int reg  = w & 1;
    int nl   = (w >> 1) & 1;
    int lane = (w >> 2) & 31;
    int ntp  = (w >> 7) & 3;
    int sq   = w >> 9;
    int s    = sq % NS;
    int q    = sq / NS;
    int t = lane & 3, g = lane >> 2;
    int n = (ntp * 2 + nl) * 8 + g;
    float v[2];
#pragma unroll
    for (int h = 0; h < 2; h++) {
        int kl = 16 * s + 2 * t + 8 * reg + h;
        int kg = q * KCH + kl;
        int i  = kg / 3, f = kg - 3 * i;
        int ij = i * OUT_DIM + n;
        v[h] = (f == 0) ? c[ij * 2] * ws[ij]
             : (f == 1) ? c[ij * 2 + 1] * ws[ij]
                        : wb[ij];
    }
    g_w2[w] = __floats2half2_rn(v[0], v[1]);
}

__device__ __forceinline__ void mma_f16(float* cc, uint32_t a0, uint32_t a1,
                                        uint32_t a2, uint32_t a3,
                                        uint32_t b0, uint32_t b1) {
    asm volatile("mma.sync.aligned.m16n8k16.row.col.f32.f16.f16.f32 "
                 "{%0,%1,%2,%3}, {%4,%5,%6,%7}, {%8,%9}, {%0,%1,%2,%3};"
                 : "+f"(cc[0]), "+f"(cc[1]), "+f"(cc[2]), "+f"(cc[3])
                 : "r"(a0), "r"(a1), "r"(a2), "r"(a3), "r"(b0), "r"(b1));
}

__device__ __forceinline__ void ldmatrix_x4(uint32_t& a0, uint32_t& a1,
                                            uint32_t& a2, uint32_t& a3, uint32_t addr) {
    asm volatile("ldmatrix.sync.aligned.m8n8.x4.shared.b16 {%0,%1,%2,%3}, [%4];"
                 : "=r"(a0), "=r"(a1), "=r"(a2), "=r"(a3) : "r"(addr));
}

__device__ __forceinline__ void cp_async16(uint32_t dst, const void* src) {
    asm volatile("cp.async.cg.shared.global [%0], [%1], 16;"
                 :: "r"(dst), "l"(__cvta_generic_to_global(src)) : "memory");
}

__device__ __forceinline__ uint32_t smem_u32(const void* p) {
    uint32_t a;
    asm("{ .reg .u64 t; cvta.to.shared.u64 t, %1; cvt.u32.u64 %0, t; }" : "=r"(a) : "l"(p));
    return a;
}

// Compute 8 x-values' features (24 halfs) and store as 3x uint4.
__device__ __forceinline__ void write_feat8(uint32_t* dst, const float* xv) {
    float fe[24];
#pragma unroll
    for (int u = 0; u < 8; u++)
        kan_features(xv[u], fe[3 * u], fe[3 * u + 1], fe[3 * u + 2]);
    uint32_t hw[12];
#pragma unroll
    for (int j = 0; j < 12; j++) {
        __half2 h = __floats2half2_rn(fe[2 * j], fe[2 * j + 1]);
        hw[j] = *(uint32_t*)&h;
    }
    ((uint4*)dst)[0] = make_uint4(hw[0], hw[1], hw[2], hw[3]);
    ((uint4*)dst)[1] = make_uint4(hw[4], hw[5], hw[6], hw[7]);
    ((uint4*)dst)[2] = make_uint4(hw[8], hw[9], hw[10], hw[11]);
}

__global__ __launch_bounds__(THREADS, 2)
void kan_main_kernel(const float* __restrict__ x, float* __restrict__ out) {
    extern __shared__ uint32_t smw[];
    uint32_t* Asm = smw;                       // [2][A_BUF_W]  row-major A
    uint32_t* Bsm = smw + 2 * A_BUF_W;         // [2][B_BUF_W]

    const int tid  = threadIdx.x;
    const int lane = tid & 31;
    const int wid  = tid >> 5;
    const int wr   = wid & 1;                  // 2 row groups of 32
    const int wc   = wid >> 1;                 // 4 col groups of 16
    const int g    = lane >> 2;
    const int t    = lane & 3;

    // feature-writer role: row frow, x-cols [16*q4, 16*q4+16)
    const int frow = tid >> 2;                 // 0..63
    const int q4   = tid & 3;
    const float* xrow = x + (size_t)(blockIdx.x * BM + frow) * IN_DIM + q4 * 16;

    // ldmatrix lane address components
    const uint32_t lrow = wr * 32 + (lane & 15);
    const uint32_t lcol = (lane >> 4) * 4;     // word offset (k-half block)
    const uint32_t AsAddr = smem_u32(Asm);
    const uint32_t BsAddr = smem_u32(Bsm);
    uint32_t* Afw = Asm + frow * A_ROW_W + q4 * 24;   // feature write base (buf 0)

    float cacc[2][2][4];
#pragma unroll
    for (int mt = 0; mt < 2; mt++)
#pragma unroll
        for (int nl = 0; nl < 2; nl++)
#pragma unroll
            for (int r = 0; r < 4; r++) cacc[mt][nl][r] = 0.0f;

    // ---- prologue: B(0) via cp.async; features(0); stage x(1) ----
    {
        const char* src = (const char*)g_w2 + tid * 16;
        uint32_t dst = BsAddr + tid * 16;
#pragma unroll
        for (int i = 0; i < 6; i++)
            cp_async16(dst + i * 4096, src + i * 4096);
        asm volatile("cp.async.commit_group;" ::: "memory");
    }

    float4 xa[4];
    {   // features(0) -> A buf 0
        float4 v0 = *(const float4*)(xrow + 0);
        float4 v1 = *(const float4*)(xrow + 4);
        float4 v2 = *(const float4*)(xrow + 8);
        float4 v3 = *(const float4*)(xrow + 12);
        float xv0[8] = {v0.x, v0.y, v0.z, v0.w, v1.x, v1.y, v1.z, v1.w};
        float xv1[8] = {v2.x, v2.y, v2.z, v2.w, v3.x, v3.y, v3.z, v3.w};
        write_feat8(Afw + 0,  xv0);
        write_feat8(Afw + 12, xv1);
        // stage x(1)
        const float* nx = xrow + XCH;
        xa[0] = *(const float4*)(nx + 0);
        xa[1] = *(const float4*)(nx + 4);
        xa[2] = *(const float4*)(nx + 8);
        xa[3] = *(const float4*)(nx + 12);
    }

    for (int ch = 0; ch < NCH2; ch++) {
        const int b = ch & 1;

        asm volatile("cp.async.wait_group 0;" ::: "memory");
        __syncthreads();   // publish features(ch) in A[b] and B(ch) in Bsm[b]

        // issue B(ch+1) into buf b^1 (its readers, MMA(ch-1), retired pre-barrier)
        {
            int nc = ch + 1 < NCH2 ? ch + 1 : NCH2 - 1;
            const char* src = (const char*)g_w2 + (size_t)nc * B_BUF_W * 4 + tid * 16;
            uint32_t dst = BsAddr + (b ^ 1) * B_BUF_W * 4 + tid * 16;
#pragma unroll
            for (int i = 0; i < 6; i++)
                cp_async16(dst + i * 4096, src + i * 4096);
            asm volatile("cp.async.commit_group;" ::: "memory");
        }

        // ---- MMA(ch): A[b] (ldmatrix) x B[b] ----
        {
            const uint32_t abase = AsAddr + b * A_BUF_W * 4 + (lrow * A_ROW_W + lcol) * 4;
            const uint32_t* Bb = Bsm + b * B_BUF_W;
#pragma unroll
            for (int s = 0; s < NS; s++) {
                uint4 bv = *(const uint4*)(Bb + ((s * 4 + wc) * 32 + lane) * 4);
#pragma unroll
                for (int mt = 0; mt < 2; mt++) {
                    uint32_t a0, a1, a2, a3;
                    ldmatrix_x4(a0, a1, a2, a3, abase + mt * (16 * A_ROW_W * 4) + s * 32);
                    mma_f16(cacc[mt][0], a0, a1, a2, a3, bv.x, bv.y);
                    mma_f16(cacc[mt][1], a0, a1, a2, a3, bv.z, bv.w);
                }
            }
        }

        // ---- features(ch+1) -> A[b^1] (tail iterations write unused data) ----
        {
            uint32_t* dst = Afw + (b ^ 1) * A_BUF_W;
            float xv0[8] = {xa[0].x, xa[0].y, xa[0].z, xa[0].w,
                            xa[1].x, xa[1].y, xa[1].z, xa[1].w};
            float xv1[8] = {xa[2].x, xa[2].y, xa[2].z, xa[2].w,
                            xa[3].x, xa[3].y, xa[3].z, xa[3].w};
            write_feat8(dst + 0,  xv0);
            write_feat8(dst + 12, xv1);
        }
        // ---- stage x(ch+2) ----
        {
            int nc = ch + 2 < NCH2 ? ch + 2 : NCH2 - 1;
            const float* nx = xrow + (size_t)nc * XCH;
            xa[0] = *(const float4*)(nx + 0);
            xa[1] = *(const float4*)(nx + 4);
            xa[2] = *(const float4*)(nx + 8);
            xa[3] = *(const float4*)(nx + 12);
        }
    }

    // ---- epilogue ----
    const int row0 = blockIdx.x * BM + wr * 32 + g;
#pragma unroll
    for (int mt = 0; mt < 2; mt++) {
#pragma unroll
        for (int nl = 0; nl < 2; nl++) {
            int rA = row0 + mt * 16;
            int cA = (wc * 2 + nl) * 8 + 2 * t;
            *(float2*)(out + (size_t)rA * OUT_DIM + cA) =
                make_float2(cacc[mt][nl][0], cacc[mt][nl][1]);
            *(float2*)(out + (size_t)(rA + 8) * OUT_DIM + cA) =
                make_float2(cacc[mt][nl][2], cacc[mt][nl][3]);
        }
    }
}

extern "C" void kernel_launch(void* const* d_in, const int* in_sizes, int n_in,
                              void* d_out, int out_size) {
    const float* x  = (const float*)d_in[0];
    const float* c  = (const float*)d_in[1];
    const float* ws = (const float*)d_in[2];
    const float* wb = (const float*)d_in[3];
    float* out = (float*)d_out;

    cudaFuncSetAttribute(kan_main_kernel, cudaFuncAttributeMaxDynamicSharedMemorySize,
                         SMEM_BYTES);

    prep_weights_kernel<<<(NCH2 * B_BUF_W + 255) / 256, 256>>>(c, ws, wb);
    kan_main_kernel<<<BATCH / BM, THREADS, SMEM_BYTES>>>(x, out);
}